// round 5
// baseline (speedup 1.0000x reference)
#include <cuda_runtime.h>
#include <math.h>
#include <stdint.h>

#define BB 32
#define HH 1024
#define EE 512
#define VV 32001
#define NSTEP 32
#define PC 32256          // padded projection cols = 126*256
#define PB 126            // projection blocks

// ---------------- device state ----------------
__device__ float d_w0T[1536 * 4096];   // layer0 gate weights, k-major, cols c'=j*4+g
__device__ float d_w1T[2048 * 4096];   // layer1 gate weights
__device__ float d_woT[1024 * PC];     // w_out k-major, padded cols (pad zeros)
__device__ float d_h[2][2][HH * BB];   // [parity][layer][j*32+b]
__device__ float d_x[EE * BB];         // embedded token, [k*32+b]
__device__ float d_cst[2 * HH * BB];   // cell state [layer][j][b]
__device__ float d_pmax[PB * BB];
__device__ int   d_pidx[PB * BB];
__device__ int   d_tok[BB];
__device__ int   d_run[BB];
__device__ int   d_len[BB];

typedef unsigned long long ull;

__device__ __forceinline__ ull pack2(float lo, float hi) {
    ull r; asm("mov.b64 %0,{%1,%2};" : "=l"(r) : "f"(lo), "f"(hi)); return r;
}
__device__ __forceinline__ ull fma2(ull a, ull b, ull c) {
    ull d; asm("fma.rn.f32x2 %0,%1,%2,%3;" : "=l"(d) : "l"(a), "l"(b), "l"(c)); return d;
}
__device__ __forceinline__ float2 unpk(ull a) {
    float2 f; asm("mov.b64 {%0,%1},%2;" : "=f"(f.x), "=f"(f.y) : "l"(a)); return f;
}
__device__ __forceinline__ void cpa16(uint32_t d, const float* s) {
    asm volatile("cp.async.cg.shared.global [%0], [%1], 16;" :: "r"(d), "l"(s));
}
__device__ __forceinline__ void cpcommit() { asm volatile("cp.async.commit_group;"); }
__device__ __forceinline__ void cpwait2() { asm volatile("cp.async.wait_group 2;"); }
__device__ __forceinline__ float4 lds128f(uint32_t a) {
    float4 v;
    asm volatile("ld.shared.v4.f32 {%0,%1,%2,%3},[%4];"
                 : "=f"(v.x), "=f"(v.y), "=f"(v.z), "=f"(v.w) : "r"(a));
    return v;
}
__device__ __forceinline__ void lds2u64(uint32_t a, ull& p, ull& q) {
    asm volatile("ld.shared.v2.b64 {%0,%1},[%2];" : "=l"(p), "=l"(q) : "r"(a));
}
__device__ __forceinline__ float lds32(uint32_t a) {
    float v; asm volatile("ld.shared.f32 %0,[%1];" : "=f"(v) : "r"(a)); return v;
}

// ---------------- fused prep: weight transposes (gate-interleaved) + init ----------------
__global__ void __launch_bounds__(256) k_prep(const float* __restrict__ wih0,
                                              const float* __restrict__ whh0,
                                              const float* __restrict__ wih1,
                                              const float* __restrict__ whh1,
                                              const float* __restrict__ wout,
                                              const float* __restrict__ h0,
                                              const float* __restrict__ c0) {
    __shared__ float tl[32][33];
    int blk = blockIdx.x;
    int t = threadIdx.x;
    if (blk < 14336) {
        const float* in; float* out; int Km, koff, mb, nk;
        if (blk < 2048)       { in = wih0; out = d_w0T; Km = 512;  koff = 0;    mb = blk;         nk = 16; }
        else if (blk < 6144)  { in = whh0; out = d_w0T; Km = 1024; koff = 512;  mb = blk - 2048;  nk = 32; }
        else if (blk < 10240) { in = wih1; out = d_w1T; Km = 1024; koff = 0;    mb = blk - 6144;  nk = 32; }
        else                  { in = whh1; out = d_w1T; Km = 1024; koff = 1024; mb = blk - 10240; nk = 32; }
        int kt = mb % nk, jt = mb / nk;
#pragma unroll
        for (int q = 0; q < 4; q++) {
            int id = t + 256 * q; int kk = id & 31; int rr = id >> 5;
            int g = rr >> 3, j = rr & 7;
            tl[kk][j * 4 + g] = in[(size_t)(g * 1024 + jt * 8 + j) * Km + kt * 32 + kk];
        }
        __syncthreads();
#pragma unroll
        for (int q = 0; q < 4; q++) {
            int id = t + 256 * q; int c = id & 31; int kk = id >> 5;
            out[(size_t)(koff + kt * 32 + kk) * 4096 + jt * 32 + c] = tl[kk][c];
        }
    } else if (blk < 46368) {
        int mb = blk - 14336; int kt = mb % 32, rt = mb / 32;   // rt < 1001
#pragma unroll
        for (int q = 0; q < 4; q++) {
            int id = t + 256 * q; int kk = id & 31; int rr = id >> 5;
            int r = rt * 32 + rr;
            tl[rr][kk] = (r < VV) ? wout[(size_t)r * 1024 + kt * 32 + kk] : 0.f;
        }
        __syncthreads();
#pragma unroll
        for (int q = 0; q < 4; q++) {
            int id = t + 256 * q; int rr = id & 31; int kk = id >> 5;
            int r = rt * 32 + rr;
            if (r < PC) d_woT[(size_t)(kt * 32 + kk) * PC + r] = tl[rr][kk];
        }
    } else {
        int i = (blk - 46368) * 256 + t;   // < 65536
        int l = i >> 15; int r = i & 32767; int bb = r >> 10; int j = r & 1023;
        d_h[0][l][j * 32 + bb] = h0[i];
        d_cst[(l * 1024 + j) * 32 + bb] = c0[i];
        if (blk == 46368 && t < 32) { d_tok[t] = 32000; d_run[t] = 1; d_len[t] = 0; }
    }
}

// ---------------- fused select (argmax) + embedding gather ----------------
__global__ void __launch_bounds__(512) k_selembed(const float* __restrict__ emb,
                                                  float* __restrict__ outp,
                                                  int has_len, int s) {
    __shared__ float sv[128];
    __shared__ int   si[128];
    int b = blockIdx.x;
    int t = threadIdx.x;

    if (s > 0) {
        if (t < 128) {
            float best = -3.402823466e38f; int bi = 0x7fffffff;
            if (t < PB) { best = d_pmax[t * BB + b]; bi = d_pidx[t * BB + b]; }
            sv[t] = best; si[t] = bi;
        }
        __syncthreads();
        if (t == 0) {
            float best = sv[0]; int bi = si[0];
            for (int p = 1; p < 128; p++) {
                float v = sv[p]; int id = si[p];
                if (v > best || (v == best && id < bi)) { best = v; bi = id; }
            }
            d_tok[b] = bi;
            int r2 = d_run[b] && (bi != 32000);
            d_run[b] = r2;
            if (r2) d_len[b] = s;
            if (has_len) outp[(size_t)NSTEP * BB * VV + b] = (float)d_len[b];
        }
        __syncthreads();
    }
    int tok = d_tok[b];
    d_x[t * BB + b] = emb[(size_t)tok * EE + t];   // t = 0..511 == EE
}

// ---------------- fused gate GEMM + LSTM update ----------------
// grid 128, 512 threads; intra-block k-split (2 halves), 3-slot cp.async ring each
// dyn smem 98304 = 2 halves x 3 slots x (8KB w + 8KB x)
__global__ void __launch_bounds__(512) k_gatesU(int layer, int parity,
                                                const float* __restrict__ bih,
                                                const float* __restrict__ bhh) {
    extern __shared__ __align__(16) char gsm[];
    uint32_t sbase = (uint32_t)__cvta_generic_to_shared(gsm);
    int t = threadIdx.x;
    int half = t >> 8;
    int t2 = t & 255;
    const float* wT = layer ? d_w1T : d_w0T;
    int K = layer ? 2048 : 1536;
    int Khalf = K >> 1;
    int NSTh = Khalf >> 6;            // 12 or 16 stages of 64 k
    int split = layer ? 1024 : 512;
    const float* xa = layer ? d_h[1 - parity][0] : d_x;
    const float* xb = layer ? d_h[parity][1] : d_h[parity][0];
    float* hout = d_h[1 - parity][layer];
    int cb = blockIdx.x * 32;
    int k0base = half * Khalf;
    uint32_t hbase = sbase + half * 49152;

    auto prefetch = [&](int s) {
        int slot = s % 3;
        uint32_t base = hbase + slot * 16384;
#pragma unroll
        for (int q = 0; q < 2; q++) {
            int p = t2 + 256 * q;          // 0..511
            int row = p >> 3, seg = p & 7;
            cpa16(base + row * 128 + seg * 16,
                  wT + (size_t)(k0base + s * 64 + row) * 4096 + cb + seg * 4);
        }
#pragma unroll
        for (int q = 0; q < 2; q++) {
            int p = t2 + 256 * q;
            int row = p >> 3, seg = p & 7;
            int kr = k0base + s * 64 + row;
            const float* src = (kr < split) ? (xa + (size_t)kr * 32 + seg * 4)
                                            : (xb + (size_t)(kr - split) * 32 + seg * 4);
            cpa16(base + 8192 + row * 128 + seg * 16, src);
        }
        cpcommit();
    };
    prefetch(0); prefetch(1); prefetch(2);

    int j = t2 >> 5, b = t2 & 31;
    int barid = half + 1;
    ull aif0 = 0ull, aif1 = 0ull, aif2 = 0ull, aif3 = 0ull;
    ull ago0 = 0ull, ago1 = 0ull, ago2 = 0ull, ago3 = 0ull;

    for (int s = 0; s < NSTh; s++) {
        cpwait2();
        asm volatile("bar.sync %0, 256;" :: "r"(barid));
        uint32_t base = hbase + (s % 3) * 16384;
        uint32_t wa = base + j * 16;
        uint32_t xadr = base + 8192 + b * 4;
#pragma unroll
        for (int kk = 0; kk < 64; kk += 4) {
            ull w0a, w0b, w1a, w1b, w2a, w2b, w3a, w3b;
            lds2u64(wa + kk * 128,       w0a, w0b);
            lds2u64(wa + kk * 128 + 128, w1a, w1b);
            lds2u64(wa + kk * 128 + 256, w2a, w2b);
            lds2u64(wa + kk * 128 + 384, w3a, w3b);
            float x0 = lds32(xadr + kk * 128);
            float x1 = lds32(xadr + kk * 128 + 128);
            float x2 = lds32(xadr + kk * 128 + 256);
            float x3 = lds32(xadr + kk * 128 + 384);
            ull xx0 = pack2(x0, x0), xx1 = pack2(x1, x1);
            ull xx2 = pack2(x2, x2), xx3 = pack2(x3, x3);
            aif0 = fma2(w0a, xx0, aif0); ago0 = fma2(w0b, xx0, ago0);
            aif1 = fma2(w1a, xx1, aif1); ago1 = fma2(w1b, xx1, ago1);
            aif2 = fma2(w2a, xx2, aif2); ago2 = fma2(w2b, xx2, ago2);
            aif3 = fma2(w3a, xx3, aif3); ago3 = fma2(w3b, xx3, ago3);
        }
        asm volatile("bar.sync %0, 256;" :: "r"(barid));
        if (s + 3 < NSTh) prefetch(s + 3); else cpcommit();
    }

    // combine the 4 ILP chains
    float2 u0 = unpk(aif0), u1 = unpk(aif1), u2 = unpk(aif2), u3 = unpk(aif3);
    float gi = (u0.x + u1.x) + (u2.x + u3.x);
    float gf = (u0.y + u1.y) + (u2.y + u3.y);
    float2 v0 = unpk(ago0), v1 = unpk(ago1), v2 = unpk(ago2), v3 = unpk(ago3);
    float gg = (v0.x + v1.x) + (v2.x + v3.x);
    float go = (v0.y + v1.y) + (v2.y + v3.y);

    // cross-half reduce through smem (reuse ring storage)
    float* ex = (float*)gsm;
    __syncthreads();
    if (half == 1) {
        ((float4*)ex)[t2] = make_float4(gi, gf, gg, go);
    }
    __syncthreads();
    if (half == 0) {
        float4 o = ((float4*)ex)[t2];
        gi += o.x; gf += o.y; gg += o.z; go += o.w;

        int jg = blockIdx.x * 8 + j;
        gi += bih[jg]        + bhh[jg];
        gf += bih[1024 + jg] + bhh[1024 + jg];
        gg += bih[2048 + jg] + bhh[2048 + jg];
        go += bih[3072 + jg] + bhh[3072 + jg];
        int ci = (layer * HH + jg) * BB + b;
        float c = d_cst[ci];
        float ig = 1.f / (1.f + expf(-gi));
        float fg = 1.f / (1.f + expf(-gf));
        float gt = tanhf(gg);
        float og = 1.f / (1.f + expf(-go));
        float c2 = fg * c + ig * gt;
        d_cst[ci] = c2;
        hout[jg * 32 + b] = og * tanhf(c2);
    }
}

// ---------------- output projection: cp.async pipelined, 2 k-halves ----------------
// grid 126, 512 threads; dyn smem 147456 (w 2x4x16KB, x 2x4x2KB)
__global__ void __launch_bounds__(512) k_proj(const float* __restrict__ bias,
                                              float* __restrict__ outp,
                                              int s_step, int parity) {
    extern __shared__ __align__(16) char psm[];
    uint32_t sbase = (uint32_t)__cvta_generic_to_shared(psm);
    int tid = threadIdx.x;
    int half = tid >> 8;
    int t = tid & 255;
    const float* h1 = d_h[1 - parity][1];
    int cb = blockIdx.x * 256;
    uint32_t wsb = sbase + half * 65536;
    uint32_t xsb = sbase + 131072 + half * 8192;
    const float* wbase = d_woT + (size_t)(half * 512) * PC + cb;
    const float* xbase = h1 + (size_t)(half * 512) * 32;
    int barid = half + 1;

    auto prefetch = [&](int s) {
        int slot = s & 3;
#pragma unroll
        for (int q = 0; q < 4; q++) {
            int p = t + 256 * q;          // 0..1023
            int row = p >> 6, seg = p & 63;
            cpa16(wsb + slot * 16384 + row * 1024 + seg * 16,
                  wbase + (size_t)(s * 16 + row) * PC + seg * 4);
        }
        if (t < 128) {
            int row = t >> 3, seg = t & 7;
            cpa16(xsb + slot * 2048 + row * 128 + seg * 16,
                  xbase + (size_t)(s * 16 + row) * 32 + seg * 4);
        }
        cpcommit();
    };
    prefetch(0); prefetch(1); prefetch(2);

    int w = t >> 5, lane = t & 31, cl = lane & 7, bg = lane >> 3;
    int col = cb + w * 32 + cl * 4;

    ull acc[4][4];
#pragma unroll
    for (int i = 0; i < 4; i++)
#pragma unroll
        for (int j = 0; j < 4; j++) acc[i][j] = 0ull;

    for (int s = 0; s < 32; s++) {
        cpwait2();
        asm volatile("bar.sync %0, 256;" :: "r"(barid));
        uint32_t wa = wsb + (s & 3) * 16384 + w * 128 + cl * 16;
        uint32_t xadr = xsb + (s & 3) * 2048 + bg * 32;
#pragma unroll
        for (int kk = 0; kk < 16; kk++) {
            float4 w4 = lds128f(wa + kk * 1024);
            ull x0, x1, x2, x3;
            lds2u64(xadr + kk * 128, x0, x1);
            lds2u64(xadr + kk * 128 + 16, x2, x3);
            ull wv0 = pack2(w4.x, w4.x), wv1 = pack2(w4.y, w4.y);
            ull wv2 = pack2(w4.z, w4.z), wv3 = pack2(w4.w, w4.w);
            acc[0][0] = fma2(wv0, x0, acc[0][0]); acc[0][1] = fma2(wv0, x1, acc[0][1]);
            acc[0][2] = fma2(wv0, x2, acc[0][2]); acc[0][3] = fma2(wv0, x3, acc[0][3]);
            acc[1][0] = fma2(wv1, x0, acc[1][0]); acc[1][1] = fma2(wv1, x1, acc[1][1]);
            acc[1][2] = fma2(wv1, x2, acc[1][2]); acc[1][3] = fma2(wv1, x3, acc[1][3]);
            acc[2][0] = fma2(wv2, x0, acc[2][0]); acc[2][1] = fma2(wv2, x1, acc[2][1]);
            acc[2][2] = fma2(wv2, x2, acc[2][2]); acc[2][3] = fma2(wv2, x3, acc[2][3]);
            acc[3][0] = fma2(wv3, x0, acc[3][0]); acc[3][1] = fma2(wv3, x1, acc[3][1]);
            acc[3][2] = fma2(wv3, x2, acc[3][2]); acc[3][3] = fma2(wv3, x3, acc[3][3]);
        }
        asm volatile("bar.sync %0, 256;" :: "r"(barid));
        if (s + 3 < 32) prefetch(s + 3); else cpcommit();
    }
    __syncthreads();

    float f[32];
#pragma unroll
    for (int i = 0; i < 4; i++)
#pragma unroll
        for (int j = 0; j < 4; j++) {
            float2 u = unpk(acc[i][j]);
            f[i * 8 + 2 * j] = u.x;
            f[i * 8 + 2 * j + 1] = u.y;
        }

    float* ex = (float*)psm;                    // 32KB exchange (reuse stage smem)
    float* rv = (float*)(psm + 32768);          // [32][64]
    int*   ri = (int*)(psm + 40960);            // [32][64]

    if (half == 1) {
        float* ps = ex + (size_t)t * 32;
#pragma unroll
        for (int i = 0; i < 32; i++) ps[(i + t) & 31] = f[i];
    }
    __syncthreads();
    if (half == 0) {
        const float* ps = ex + (size_t)t * 32;
#pragma unroll
        for (int i = 0; i < 32; i++) f[i] += ps[(i + t) & 31];

        float bv[8]; int bx[8];
#pragma unroll
        for (int j = 0; j < 8; j++) { bv[j] = -3.402823466e38f; bx[j] = VV; }
#pragma unroll
        for (int i = 0; i < 4; i++) {
            int c = col + i;
            if (c < VV) {
                float bb = bias[c];
#pragma unroll
                for (int j = 0; j < 4; j++) {
                    float ux = f[i * 8 + 2 * j] + bb;
                    float uy = f[i * 8 + 2 * j + 1] + bb;
                    size_t o0 = (size_t)s_step * BB * VV + (size_t)(bg * 8 + 2 * j) * VV + c;
                    outp[o0] = ux;
                    outp[o0 + VV] = uy;
                    if (ux > bv[2 * j]     || (ux == bv[2 * j]     && c < bx[2 * j]))     { bv[2 * j] = ux;     bx[2 * j] = c; }
                    if (uy > bv[2 * j + 1] || (uy == bv[2 * j + 1] && c < bx[2 * j + 1])) { bv[2 * j + 1] = uy; bx[2 * j + 1] = c; }
                }
            }
        }
        int slot = w * 8 + cl;
#pragma unroll
        for (int j = 0; j < 8; j++) { rv[(bg * 8 + j) * 64 + slot] = bv[j]; ri[(bg * 8 + j) * 64 + slot] = bx[j]; }
    }
    __syncthreads();

    if (tid < BB) {
        float best = -3.402823466e38f; int bi = VV;
        for (int p = 0; p < 64; p++) {
            float v = rv[tid * 64 + p]; int id = ri[tid * 64 + p];
            if (v > best || (v == best && id < bi)) { best = v; bi = id; }
        }
        d_pmax[blockIdx.x * BB + tid] = best;
        d_pidx[blockIdx.x * BB + tid] = bi;
    }
}

// ---------------- launch ----------------
extern "C" void kernel_launch(void* const* d_in, const int* in_sizes, int n_in,
                              void* d_out, int out_size) {
    const float* h0   = (const float*)d_in[2];
    const float* c0   = (const float*)d_in[3];
    const float* emb  = (const float*)d_in[4];
    const float* wih0 = (const float*)d_in[5];
    const float* whh0 = (const float*)d_in[6];
    const float* bih0 = (const float*)d_in[7];
    const float* bhh0 = (const float*)d_in[8];
    const float* wih1 = (const float*)d_in[9];
    const float* whh1 = (const float*)d_in[10];
    const float* bih1 = (const float*)d_in[11];
    const float* bhh1 = (const float*)d_in[12];
    const float* wout = (const float*)d_in[13];
    const float* bout = (const float*)d_in[14];
    float* outp = (float*)d_out;
    int has_len = out_size > NSTEP * BB * VV;

    cudaFuncSetAttribute(k_gatesU, cudaFuncAttributeMaxDynamicSharedMemorySize, 98304);
    cudaFuncSetAttribute(k_proj, cudaFuncAttributeMaxDynamicSharedMemorySize, 147456);

    k_prep<<<46624, 256>>>(wih0, whh0, wih1, whh1, wout, h0, c0);

    for (int s = 0; s < NSTEP; s++) {
        int p = s & 1;
        k_selembed<<<BB, 512>>>(emb, outp, has_len, s);
        k_gatesU<<<128, 512, 98304>>>(0, p, bih0, bhh0);
        k_gatesU<<<128, 512, 98304>>>(1, p, bih1, bhh1);
        k_proj<<<PB, 512, 147456>>>(bout, outp, s, p);
    }
    k_selembed<<<BB, 512>>>(emb, outp, has_len, NSTEP);
}

// round 9
// speedup vs baseline: 1.8705x; 1.8705x over previous
#include <cuda_runtime.h>
#include <math.h>
#include <stdint.h>

#define BB 32
#define HH 1024
#define EE 512
#define VV 32001
#define NSTEP 32
#define PC 32256          // padded projection cols = 126*256
#define PB 126            // projection blocks
#define KSPL 8            // k-split for gate GEMMs

// ---------------- device state ----------------
__device__ float d_w0T[1536 * 4096];   // layer0 gate weights, k-major, cols c'=(unit/8)*32+(unit%8)*4+g
__device__ float d_w1T[2048 * 4096];   // layer1 gate weights
__device__ float d_woT[1024 * PC];     // w_out k-major, padded cols (pad zeros)
__device__ float d_h[2][2][HH * BB];   // [parity][layer][j*32+b]
__device__ float d_x[EE * BB];         // embedded token, [k*32+b]
__device__ float d_cst[2 * HH * BB];   // cell state [layer][j][b]
__device__ float d_gp[KSPL * 4096 * BB]; // gate GEMM partials [ks][col][b]
__device__ float d_pmax[PB * BB];
__device__ int   d_pidx[PB * BB];
__device__ int   d_tok[BB];
__device__ int   d_run[BB];
__device__ int   d_len[BB];

typedef unsigned long long ull;

__device__ __forceinline__ ull pack2(float lo, float hi) {
    ull r; asm("mov.b64 %0,{%1,%2};" : "=l"(r) : "f"(lo), "f"(hi)); return r;
}
__device__ __forceinline__ ull fma2(ull a, ull b, ull c) {
    ull d; asm("fma.rn.f32x2 %0,%1,%2,%3;" : "=l"(d) : "l"(a), "l"(b), "l"(c)); return d;
}
__device__ __forceinline__ float2 unpk(ull a) {
    float2 f; asm("mov.b64 {%0,%1},%2;" : "=f"(f.x), "=f"(f.y) : "l"(a)); return f;
}
__device__ __forceinline__ void cpa16(uint32_t d, const float* s) {
    asm volatile("cp.async.cg.shared.global [%0], [%1], 16;" :: "r"(d), "l"(s));
}
__device__ __forceinline__ void cpcommit() { asm volatile("cp.async.commit_group;"); }
__device__ __forceinline__ void cpwait2() { asm volatile("cp.async.wait_group 2;"); }
__device__ __forceinline__ float4 lds128f(uint32_t a) {
    float4 v;
    asm volatile("ld.shared.v4.f32 {%0,%1,%2,%3},[%4];"
                 : "=f"(v.x), "=f"(v.y), "=f"(v.z), "=f"(v.w) : "r"(a));
    return v;
}
__device__ __forceinline__ void lds2u64(uint32_t a, ull& p, ull& q) {
    asm volatile("ld.shared.v2.b64 {%0,%1},[%2];" : "=l"(p), "=l"(q) : "r"(a));
}

// ---------------- fused prep: weight transposes (gate-interleaved) + init ----------------
__global__ void __launch_bounds__(256) k_prep(const float* __restrict__ wih0,
                                              const float* __restrict__ whh0,
                                              const float* __restrict__ wih1,
                                              const float* __restrict__ whh1,
                                              const float* __restrict__ wout,
                                              const float* __restrict__ h0,
                                              const float* __restrict__ c0) {
    __shared__ float tl[32][33];
    int blk = blockIdx.x;
    int t = threadIdx.x;
    if (blk < 14336) {
        const float* in; float* out; int Km, koff, mb, nk;
        if (blk < 2048)       { in = wih0; out = d_w0T; Km = 512;  koff = 0;    mb = blk;         nk = 16; }
        else if (blk < 6144)  { in = whh0; out = d_w0T; Km = 1024; koff = 512;  mb = blk - 2048;  nk = 32; }
        else if (blk < 10240) { in = wih1; out = d_w1T; Km = 1024; koff = 0;    mb = blk - 6144;  nk = 32; }
        else                  { in = whh1; out = d_w1T; Km = 1024; koff = 1024; mb = blk - 10240; nk = 32; }
        int kt = mb % nk, jt = mb / nk;
#pragma unroll
        for (int q = 0; q < 4; q++) {
            int id = t + 256 * q; int kk = id & 31; int rr = id >> 5;
            int g = rr >> 3, j = rr & 7;
            tl[kk][j * 4 + g] = in[(size_t)(g * 1024 + jt * 8 + j) * Km + kt * 32 + kk];
        }
        __syncthreads();
#pragma unroll
        for (int q = 0; q < 4; q++) {
            int id = t + 256 * q; int c = id & 31; int kk = id >> 5;
            out[(size_t)(koff + kt * 32 + kk) * 4096 + jt * 32 + c] = tl[kk][c];
        }
    } else if (blk < 46368) {
        int mb = blk - 14336; int kt = mb % 32, rt = mb / 32;   // rt < 1001
#pragma unroll
        for (int q = 0; q < 4; q++) {
            int id = t + 256 * q; int kk = id & 31; int rr = id >> 5;
            int r = rt * 32 + rr;
            tl[rr][kk] = (r < VV) ? wout[(size_t)r * 1024 + kt * 32 + kk] : 0.f;
        }
        __syncthreads();
#pragma unroll
        for (int q = 0; q < 4; q++) {
            int id = t + 256 * q; int rr = id & 31; int kk = id >> 5;
            int r = rt * 32 + rr;
            if (r < PC) d_woT[(size_t)(kt * 32 + kk) * PC + r] = tl[rr][kk];
        }
    } else {
        int i = (blk - 46368) * 256 + t;   // < 65536
        int l = i >> 15; int r = i & 32767; int bb = r >> 10; int j = r & 1023;
        d_h[0][l][j * 32 + bb] = h0[i];
        d_cst[(l * 1024 + j) * 32 + bb] = c0[i];
        if (blk == 46368 && t < 32) { d_tok[t] = 32000; d_run[t] = 1; d_len[t] = 0; }
    }
}

// ---------------- fused select (argmax) + embedding gather ----------------
__global__ void __launch_bounds__(512) k_selembed(const float* __restrict__ emb,
                                                  float* __restrict__ outp,
                                                  int has_len, int s) {
    __shared__ float sv[128];
    __shared__ int   si[128];
    int b = blockIdx.x;
    int t = threadIdx.x;

    if (s > 0) {
        if (t < 128) {
            float best = -3.402823466e38f; int bi = 0x7fffffff;
            if (t < PB) { best = d_pmax[t * BB + b]; bi = d_pidx[t * BB + b]; }
            sv[t] = best; si[t] = bi;
        }
        __syncthreads();
        if (t == 0) {
            float best = sv[0]; int bi = si[0];
            for (int p = 1; p < 128; p++) {
                float v = sv[p]; int id = si[p];
                if (v > best || (v == best && id < bi)) { best = v; bi = id; }
            }
            d_tok[b] = bi;
            int r2 = d_run[b] && (bi != 32000);
            d_run[b] = r2;
            if (r2) d_len[b] = s;
            if (has_len) outp[(size_t)NSTEP * BB * VV + b] = (float)d_len[b];
        }
        __syncthreads();
    }
    int tok = d_tok[b];
    d_x[t * BB + b] = emb[(size_t)tok * EE + t];   // t = 0..511 == EE
}

// ---------------- gate GEMM: proj-style tiles, k-split partials ----------------
// grid (16 colblocks, 8 k-slices), 256 threads; dyn smem 73728 = 4x(16KB w + 2KB x)
__global__ void __launch_bounds__(256) k_gates2(int layer, int parity) {
    extern __shared__ __align__(16) char gsm[];
    uint32_t sbase = (uint32_t)__cvta_generic_to_shared(gsm);
    uint32_t wsb = sbase;            // 4 slots x 16KB
    uint32_t xsb = sbase + 65536;    // 4 slots x 2KB
    int t = threadIdx.x;
    const float* wT = layer ? d_w1T : d_w0T;
    int K = layer ? 2048 : 1536;
    int Kslice = K >> 3;             // 256 or 192
    int NST = Kslice >> 4;           // 16 or 12 stages of 16 k
    int split = layer ? 1024 : 512;
    const float* xa = layer ? d_h[1 - parity][0] : d_x;
    const float* xb = layer ? d_h[parity][1] : d_h[parity][0];
    int cb = blockIdx.x * 256;
    int k0 = blockIdx.y * Kslice;

    auto prefetch = [&](int s) {
        int slot = s & 3;
#pragma unroll
        for (int q = 0; q < 4; q++) {
            int p = t + 256 * q;          // 0..1023
            int row = p >> 6, seg = p & 63;
            cpa16(wsb + slot * 16384 + row * 1024 + seg * 16,
                  wT + (size_t)(k0 + s * 16 + row) * 4096 + cb + seg * 4);
        }
        if (t < 128) {
            int row = t >> 3, seg = t & 7;
            int kr = k0 + s * 16 + row;
            const float* src = (kr < split) ? (xa + (size_t)kr * 32 + seg * 4)
                                            : (xb + (size_t)(kr - split) * 32 + seg * 4);
            cpa16(xsb + slot * 2048 + row * 128 + seg * 16, src);
        }
        cpcommit();
    };
    prefetch(0); prefetch(1); prefetch(2);

    int w = t >> 5, lane = t & 31, cl = lane & 7, bg = lane >> 3;
    int col = cb + w * 32 + cl * 4;

    ull acc[4][4];
#pragma unroll
    for (int i = 0; i < 4; i++)
#pragma unroll
        for (int j = 0; j < 4; j++) acc[i][j] = 0ull;

    for (int s = 0; s < NST; s++) {
        cpwait2();
        __syncthreads();
        uint32_t wa = wsb + (s & 3) * 16384 + w * 128 + cl * 16;
        uint32_t xadr = xsb + (s & 3) * 2048 + bg * 32;
#pragma unroll
        for (int kk = 0; kk < 16; kk++) {
            float4 w4 = lds128f(wa + kk * 1024);
            ull x0, x1, x2, x3;
            lds2u64(xadr + kk * 128, x0, x1);
            lds2u64(xadr + kk * 128 + 16, x2, x3);
            ull wv0 = pack2(w4.x, w4.x), wv1 = pack2(w4.y, w4.y);
            ull wv2 = pack2(w4.z, w4.z), wv3 = pack2(w4.w, w4.w);
            acc[0][0] = fma2(wv0, x0, acc[0][0]); acc[0][1] = fma2(wv0, x1, acc[0][1]);
            acc[0][2] = fma2(wv0, x2, acc[0][2]); acc[0][3] = fma2(wv0, x3, acc[0][3]);
            acc[1][0] = fma2(wv1, x0, acc[1][0]); acc[1][1] = fma2(wv1, x1, acc[1][1]);
            acc[1][2] = fma2(wv1, x2, acc[1][2]); acc[1][3] = fma2(wv1, x3, acc[1][3]);
            acc[2][0] = fma2(wv2, x0, acc[2][0]); acc[2][1] = fma2(wv2, x1, acc[2][1]);
            acc[2][2] = fma2(wv2, x2, acc[2][2]); acc[2][3] = fma2(wv2, x3, acc[2][3]);
            acc[3][0] = fma2(wv3, x0, acc[3][0]); acc[3][1] = fma2(wv3, x1, acc[3][1]);
            acc[3][2] = fma2(wv3, x2, acc[3][2]); acc[3][3] = fma2(wv3, x3, acc[3][3]);
        }
        __syncthreads();
        if (s + 3 < NST) prefetch(s + 3); else cpcommit();
    }

#pragma unroll
    for (int i = 0; i < 4; i++) {
        size_t base = ((size_t)blockIdx.y * 4096 + col + i) * BB + bg * 8;
        *(ull*)(d_gp + base)     = acc[i][0];
        *(ull*)(d_gp + base + 2) = acc[i][1];
        *(ull*)(d_gp + base + 4) = acc[i][2];
        *(ull*)(d_gp + base + 6) = acc[i][3];
    }
}

// ---------------- LSTM elementwise update (partials reduce + nonlinearity) ----------------
__global__ void k_update2(const float* __restrict__ bih, const float* __restrict__ bhh,
                          int layer, int parity) {
    int g = blockIdx.x * 256 + threadIdx.x;   // 32768
    int unit = g >> 5, b = g & 31;
    int colb = (unit >> 3) * 32 + (unit & 7) * 4;   // gate-interleaved base col
    float a[4];
#pragma unroll
    for (int q = 0; q < 4; q++) a[q] = bih[q * 1024 + unit] + bhh[q * 1024 + unit];
#pragma unroll
    for (int ks = 0; ks < KSPL; ks++)
#pragma unroll
        for (int q = 0; q < 4; q++)
            a[q] += d_gp[((size_t)ks * 4096 + colb + q) * BB + b];

    int ci = (layer * HH + unit) * BB + b;
    float c = d_cst[ci];
    float ig = 1.f / (1.f + expf(-a[0]));
    float fg = 1.f / (1.f + expf(-a[1]));
    float gt = tanhf(a[2]);
    float og = 1.f / (1.f + expf(-a[3]));
    float c2 = fg * c + ig * gt;
    d_cst[ci] = c2;
    d_h[1 - parity][layer][unit * 32 + b] = og * tanhf(c2);
}

// ---------------- output projection: cp.async pipelined, 2 k-halves ----------------
// grid 126, 512 threads; dyn smem 147456 (w 2x4x16KB, x 2x4x2KB)
__global__ void __launch_bounds__(512) k_proj(const float* __restrict__ bias,
                                              float* __restrict__ outp,
                                              int s_step, int parity) {
    extern __shared__ __align__(16) char psm[];
    uint32_t sbase = (uint32_t)__cvta_generic_to_shared(psm);
    int tid = threadIdx.x;
    int half = tid >> 8;
    int t = tid & 255;
    const float* h1 = d_h[1 - parity][1];
    int cb = blockIdx.x * 256;
    uint32_t wsb = sbase + half * 65536;
    uint32_t xsb = sbase + 131072 + half * 8192;
    const float* wbase = d_woT + (size_t)(half * 512) * PC + cb;
    const float* xbase = h1 + (size_t)(half * 512) * 32;
    int barid = half + 1;

    auto prefetch = [&](int s) {
        int slot = s & 3;
#pragma unroll
        for (int q = 0; q < 4; q++) {
            int p = t + 256 * q;          // 0..1023
            int row = p >> 6, seg = p & 63;
            cpa16(wsb + slot * 16384 + row * 1024 + seg * 16,
                  wbase + (size_t)(s * 16 + row) * PC + seg * 4);
        }
        if (t < 128) {
            int row = t >> 3, seg = t & 7;
            cpa16(xsb + slot * 2048 + row * 128 + seg * 16,
                  xbase + (size_t)(s * 16 + row) * 32 + seg * 4);
        }
        cpcommit();
    };
    prefetch(0); prefetch(1); prefetch(2);

    int w = t >> 5, lane = t & 31, cl = lane & 7, bg = lane >> 3;
    int col = cb + w * 32 + cl * 4;

    ull acc[4][4];
#pragma unroll
    for (int i = 0; i < 4; i++)
#pragma unroll
        for (int j = 0; j < 4; j++) acc[i][j] = 0ull;

    for (int s = 0; s < 32; s++) {
        cpwait2();
        asm volatile("bar.sync %0, 256;" :: "r"(barid));
        uint32_t wa = wsb + (s & 3) * 16384 + w * 128 + cl * 16;
        uint32_t xadr = xsb + (s & 3) * 2048 + bg * 32;
#pragma unroll
        for (int kk = 0; kk < 16; kk++) {
            float4 w4 = lds128f(wa + kk * 1024);
            ull x0, x1, x2, x3;
            lds2u64(xadr + kk * 128, x0, x1);
            lds2u64(xadr + kk * 128 + 16, x2, x3);
            ull wv0 = pack2(w4.x, w4.x), wv1 = pack2(w4.y, w4.y);
            ull wv2 = pack2(w4.z, w4.z), wv3 = pack2(w4.w, w4.w);
            acc[0][0] = fma2(wv0, x0, acc[0][0]); acc[0][1] = fma2(wv0, x1, acc[0][1]);
            acc[0][2] = fma2(wv0, x2, acc[0][2]); acc[0][3] = fma2(wv0, x3, acc[0][3]);
            acc[1][0] = fma2(wv1, x0, acc[1][0]); acc[1][1] = fma2(wv1, x1, acc[1][1]);
            acc[1][2] = fma2(wv1, x2, acc[1][2]); acc[1][3] = fma2(wv1, x3, acc[1][3]);
            acc[2][0] = fma2(wv2, x0, acc[2][0]); acc[2][1] = fma2(wv2, x1, acc[2][1]);
            acc[2][2] = fma2(wv2, x2, acc[2][2]); acc[2][3] = fma2(wv2, x3, acc[2][3]);
            acc[3][0] = fma2(wv3, x0, acc[3][0]); acc[3][1] = fma2(wv3, x1, acc[3][1]);
            acc[3][2] = fma2(wv3, x2, acc[3][2]); acc[3][3] = fma2(wv3, x3, acc[3][3]);
        }
        asm volatile("bar.sync %0, 256;" :: "r"(barid));
        if (s + 3 < 32) prefetch(s + 3); else cpcommit();
    }
    __syncthreads();

    float f[32];
#pragma unroll
    for (int i = 0; i < 4; i++)
#pragma unroll
        for (int j = 0; j < 4; j++) {
            float2 u = unpk(acc[i][j]);
            f[i * 8 + 2 * j] = u.x;
            f[i * 8 + 2 * j + 1] = u.y;
        }

    float* ex = (float*)psm;                    // 32KB exchange (reuse stage smem)
    float* rv = (float*)(psm + 32768);          // [32][64]
    int*   ri = (int*)(psm + 40960);            // [32][64]

    if (half == 1) {
        float* ps = ex + (size_t)t * 32;
#pragma unroll
        for (int i = 0; i < 32; i++) ps[(i + t) & 31] = f[i];
    }
    __syncthreads();
    if (half == 0) {
        const float* ps = ex + (size_t)t * 32;
#pragma unroll
        for (int i = 0; i < 32; i++) f[i] += ps[(i + t) & 31];

        float bv[8]; int bx[8];
#pragma unroll
        for (int j = 0; j < 8; j++) { bv[j] = -3.402823466e38f; bx[j] = VV; }
#pragma unroll
        for (int i = 0; i < 4; i++) {
            int c = col + i;
            if (c < VV) {
                float bb = bias[c];
#pragma unroll
                for (int j = 0; j < 4; j++) {
                    float ux = f[i * 8 + 2 * j] + bb;
                    float uy = f[i * 8 + 2 * j + 1] + bb;
                    size_t o0 = (size_t)s_step * BB * VV + (size_t)(bg * 8 + 2 * j) * VV + c;
                    outp[o0] = ux;
                    outp[o0 + VV] = uy;
                    if (ux > bv[2 * j]     || (ux == bv[2 * j]     && c < bx[2 * j]))     { bv[2 * j] = ux;     bx[2 * j] = c; }
                    if (uy > bv[2 * j + 1] || (uy == bv[2 * j + 1] && c < bx[2 * j + 1])) { bv[2 * j + 1] = uy; bx[2 * j + 1] = c; }
                }
            }
        }
        int slot = w * 8 + cl;
#pragma unroll
        for (int j = 0; j < 8; j++) { rv[(bg * 8 + j) * 64 + slot] = bv[j]; ri[(bg * 8 + j) * 64 + slot] = bx[j]; }
    }
    __syncthreads();

    if (tid < BB) {
        float best = -3.402823466e38f; int bi = VV;
        for (int p = 0; p < 64; p++) {
            float v = rv[tid * 64 + p]; int id = ri[tid * 64 + p];
            if (v > best || (v == best && id < bi)) { best = v; bi = id; }
        }
        d_pmax[blockIdx.x * BB + tid] = best;
        d_pidx[blockIdx.x * BB + tid] = bi;
    }
}

// ---------------- launch ----------------
extern "C" void kernel_launch(void* const* d_in, const int* in_sizes, int n_in,
                              void* d_out, int out_size) {
    const float* h0   = (const float*)d_in[2];
    const float* c0   = (const float*)d_in[3];
    const float* emb  = (const float*)d_in[4];
    const float* wih0 = (const float*)d_in[5];
    const float* whh0 = (const float*)d_in[6];
    const float* bih0 = (const float*)d_in[7];
    const float* bhh0 = (const float*)d_in[8];
    const float* wih1 = (const float*)d_in[9];
    const float* whh1 = (const float*)d_in[10];
    const float* bih1 = (const float*)d_in[11];
    const float* bhh1 = (const float*)d_in[12];
    const float* wout = (const float*)d_in[13];
    const float* bout = (const float*)d_in[14];
    float* outp = (float*)d_out;
    int has_len = out_size > NSTEP * BB * VV;

    cudaFuncSetAttribute(k_gates2, cudaFuncAttributeMaxDynamicSharedMemorySize, 73728);
    cudaFuncSetAttribute(k_proj, cudaFuncAttributeMaxDynamicSharedMemorySize, 147456);

    k_prep<<<46624, 256>>>(wih0, whh0, wih1, whh1, wout, h0, c0);

    for (int s = 0; s < NSTEP; s++) {
        int p = s & 1;
        k_selembed<<<BB, 512>>>(emb, outp, has_len, s);
        k_gates2<<<dim3(16, KSPL), 256, 73728>>>(0, p);
        k_update2<<<128, 256>>>(bih0, bhh0, 0, p);
        k_gates2<<<dim3(16, KSPL), 256, 73728>>>(1, p);
        k_update2<<<128, 256>>>(bih1, bhh1, 1, p);
        k_proj<<<PB, 512, 147456>>>(bout, outp, s, p);
    }
    k_selembed<<<BB, 512>>>(emb, outp, has_len, NSTEP);
}